// round 1
// baseline (speedup 1.0000x reference)
#include <cuda_runtime.h>
#include <math.h>

// HierarchicalSoftmax: levels [16, 256, 4096], D=2048.
// out layout: [B, 4368] all_log_probs (lp0|lp1|lp2) followed by [B, 4096] lp2.
//
// K0: lp0 = logsoftmax(x@W0^T + b0)                -> out[:, 0:16]
// K1: lp1 = logsoftmax_groups16(x@W1^T + b1) + lp0 -> out[:, 16:272]   (reads lp0 from out)
// K2: lp2 = logsoftmax_groups16(x@W2^T + b2) + lp1 -> out[:, 272:4368] and out2 region

namespace {

constexpr int D_       = 2048;
constexpr int BM       = 128;
constexpr int BK       = 16;
constexpr int NTHREADS = 256;
constexpr int OW       = 4368;   // 16 + 256 + 4096

template <int BN, int LEVEL>
__global__ __launch_bounds__(NTHREADS)
void hs_gemm(const float* __restrict__ x, const float* __restrict__ W,
             const float* __restrict__ bias, float* __restrict__ out, int B)
{
    constexpr int TN  = BN / 16;            // cols per thread (1 or 4)
    constexpr int TM  = BM / 16;            // rows per thread (8)
    constexpr int AST = BM + 4;             // smem A row stride (132, mult of 4)
    constexpr int BST = BN + 4;             // smem B row stride (mult of 4)
    constexpr int ALD = BM * BK / (NTHREADS * 4);   // float4 A loads per thread (2)
    constexpr int BLD = BN * BK / NTHREADS;          // scalar B loads per thread (4 or 1)
    constexpr int SM_GEMM = 2 * BK * AST + 2 * BK * BST;
    constexpr int EST = BN + 4;
    constexpr int SM_EPI = BM * EST;
    constexpr int SM_SZ  = (SM_GEMM > SM_EPI) ? SM_GEMM : SM_EPI;

    __shared__ float sm[SM_SZ];
    float* Asm = sm;
    float* Bsm = sm + 2 * BK * AST;

    const int tid  = threadIdx.x;
    const int tx   = tid & 15;
    const int ty   = tid >> 4;
    const int row0 = blockIdx.y * BM;
    const int n0   = blockIdx.x * BN;

    const float* xblk = x + (size_t)row0 * D_;
    const float* wblk = W + (size_t)n0 * D_;

    float acc[TM][TN];
#pragma unroll
    for (int r = 0; r < TM; r++)
#pragma unroll
        for (int c = 0; c < TN; c++) acc[r][c] = 0.f;

    float4 apre[ALD];
    float  bpre[BLD];

    // ---- prefetch tile 0 ----
#pragma unroll
    for (int i = 0; i < ALD; i++) {
        int idx = tid + i * NTHREADS;
        int r = idx >> 2, kq = idx & 3;
        apre[i] = *reinterpret_cast<const float4*>(xblk + (size_t)r * D_ + kq * 4);
    }
#pragma unroll
    for (int i = 0; i < BLD; i++) {
        int idx = tid + i * NTHREADS;
        int k = idx & 15, n = idx >> 4;
        bpre[i] = wblk[(size_t)n * D_ + k];
    }
    // ---- store tile 0 into buffer 0 ----
    {
        float* Ab = Asm;
        float* Bb = Bsm;
#pragma unroll
        for (int i = 0; i < ALD; i++) {
            int idx = tid + i * NTHREADS;
            int r = idx >> 2, kq = idx & 3;
            Ab[(kq * 4 + 0) * AST + r] = apre[i].x;
            Ab[(kq * 4 + 1) * AST + r] = apre[i].y;
            Ab[(kq * 4 + 2) * AST + r] = apre[i].z;
            Ab[(kq * 4 + 3) * AST + r] = apre[i].w;
        }
#pragma unroll
        for (int i = 0; i < BLD; i++) {
            int idx = tid + i * NTHREADS;
            int k = idx & 15, n = idx >> 4;
            Bb[k * BST + n] = bpre[i];
        }
    }
    __syncthreads();

    const int NK = D_ / BK;   // 128
    for (int t = 0; t < NK; t++) {
        const int cur = t & 1;
        const int nxt = cur ^ 1;

        // prefetch next tile (global -> regs) while computing current
        if (t + 1 < NK) {
            const int k0 = (t + 1) * BK;
#pragma unroll
            for (int i = 0; i < ALD; i++) {
                int idx = tid + i * NTHREADS;
                int r = idx >> 2, kq = idx & 3;
                apre[i] = *reinterpret_cast<const float4*>(xblk + (size_t)r * D_ + k0 + kq * 4);
            }
#pragma unroll
            for (int i = 0; i < BLD; i++) {
                int idx = tid + i * NTHREADS;
                int k = idx & 15, n = idx >> 4;
                bpre[i] = wblk[(size_t)n * D_ + k0 + k];
            }
        }

        const float* Ab = Asm + cur * BK * AST;
        const float* Bb = Bsm + cur * BK * BST;

#pragma unroll
        for (int kk = 0; kk < BK; kk++) {
            float a[TM];
            const float4* ap = reinterpret_cast<const float4*>(Ab + kk * AST + ty * TM);
            float4 a0 = ap[0];
            float4 a1 = ap[1];
            a[0] = a0.x; a[1] = a0.y; a[2] = a0.z; a[3] = a0.w;
            a[4] = a1.x; a[5] = a1.y; a[6] = a1.z; a[7] = a1.w;

            float b[TN];
            if (TN == 4) {
                float4 bv = *reinterpret_cast<const float4*>(Bb + kk * BST + tx * TN);
                b[0] = bv.x; b[1] = bv.y; b[2] = bv.z; b[3] = bv.w;
            } else {
#pragma unroll
                for (int c = 0; c < TN; c++) b[c] = Bb[kk * BST + tx * TN + c];
            }
#pragma unroll
            for (int r = 0; r < TM; r++)
#pragma unroll
                for (int c = 0; c < TN; c++)
                    acc[r][c] += a[r] * b[c];
        }

        if (t + 1 < NK) {
            float* Ab2 = Asm + nxt * BK * AST;
            float* Bb2 = Bsm + nxt * BK * BST;
#pragma unroll
            for (int i = 0; i < ALD; i++) {
                int idx = tid + i * NTHREADS;
                int r = idx >> 2, kq = idx & 3;
                Ab2[(kq * 4 + 0) * AST + r] = apre[i].x;
                Ab2[(kq * 4 + 1) * AST + r] = apre[i].y;
                Ab2[(kq * 4 + 2) * AST + r] = apre[i].z;
                Ab2[(kq * 4 + 3) * AST + r] = apre[i].w;
            }
#pragma unroll
            for (int i = 0; i < BLD; i++) {
                int idx = tid + i * NTHREADS;
                int k = idx & 15, n = idx >> 4;
                Bb2[k * BST + n] = bpre[i];
            }
        }
        __syncthreads();
    }

    // ---- epilogue: bias, restage logits to smem, groupwise log-softmax ----
    float bv[TN];
#pragma unroll
    for (int c = 0; c < TN; c++) bv[c] = bias[n0 + tx * TN + c];

    float* S = sm;   // [BM][EST]
#pragma unroll
    for (int r = 0; r < TM; r++)
#pragma unroll
        for (int c = 0; c < TN; c++)
            S[(ty * TM + r) * EST + tx * TN + c] = acc[r][c] + bv[c];
    __syncthreads();

    constexpr int GROUPS = BN / 16;
    const int ntask = BM * GROUPS;
    for (int task = tid; task < ntask; task += NTHREADS) {
        const int lr = task & (BM - 1);
        const int g  = task >> 7;        // BM == 128
        const float* p = S + lr * EST + g * 16;

        float m = p[0];
#pragma unroll
        for (int j = 1; j < 16; j++) m = fmaxf(m, p[j]);
        float s = 0.f;
#pragma unroll
        for (int j = 0; j < 16; j++) s += expf(p[j] - m);
        const float lse = m + logf(s);

        const int grow = row0 + lr;
        const int gc   = n0 + g * 16;

        float pl = 0.f;
        if (LEVEL == 1) pl = out[(size_t)grow * OW + (gc >> 4)];
        if (LEVEL == 2) pl = out[(size_t)grow * OW + 16 + (gc >> 4)];

        float* o1;
        if (LEVEL == 0)      o1 = out + (size_t)grow * OW + gc;
        else if (LEVEL == 1) o1 = out + (size_t)grow * OW + 16 + gc;
        else                 o1 = out + (size_t)grow * OW + 272 + gc;

        float* o2 = nullptr;
        if (LEVEL == 2)
            o2 = out + (size_t)B * OW + (size_t)grow * 4096 + gc;

#pragma unroll
        for (int jq = 0; jq < 4; jq++) {
            float4 v;
            v.x = p[jq * 4 + 0] - lse + pl;
            v.y = p[jq * 4 + 1] - lse + pl;
            v.z = p[jq * 4 + 2] - lse + pl;
            v.w = p[jq * 4 + 3] - lse + pl;
            reinterpret_cast<float4*>(o1)[jq] = v;
            if (LEVEL == 2)
                reinterpret_cast<float4*>(o2)[jq] = v;
        }
    }
}

} // namespace

extern "C" void kernel_launch(void* const* d_in, const int* in_sizes, int n_in,
                              void* d_out, int out_size)
{
    const float* x  = (const float*)d_in[0];
    const float* W0 = (const float*)d_in[1];
    const float* b0 = (const float*)d_in[2];
    const float* W1 = (const float*)d_in[3];
    const float* b1 = (const float*)d_in[4];
    const float* W2 = (const float*)d_in[5];
    const float* b2 = (const float*)d_in[6];
    float* out = (float*)d_out;

    const int B = in_sizes[0] / D_;   // 4096
    dim3 blk(NTHREADS);

    // level 0: N=16
    hs_gemm<16, 0><<<dim3(1,            B / BM), blk>>>(x, W0, b0, out, B);
    // level 1: N=256
    hs_gemm<64, 1><<<dim3(256 / 64,     B / BM), blk>>>(x, W1, b1, out, B);
    // level 2: N=4096
    hs_gemm<64, 2><<<dim3(4096 / 64,    B / BM), blk>>>(x, W2, b2, out, B);
}

// round 3
// speedup vs baseline: 3.9156x; 3.9156x over previous
#include <cuda_runtime.h>
#include <cstdint>
#include <math.h>

// HierarchicalSoftmax, levels [16,256,4096], D=2048, B=4096.
// tf32 mma.sync (sm_80-compatible) + cp.async 3-stage pipeline + fused
// group-of-16 log-softmax epilogue. Level chain through d_out:
//   K0: lp0 -> out[:,0:16]
//   K1: lp1 = lsm16(x@W1^T+b1)+lp0 -> out[:,16:272]
//   K2: lp2 = lsm16(x@W2^T+b2)+lp1 -> out[:,272:4368] and out[B*OW:]

namespace {

constexpr int D_  = 2048;
constexpr int BM  = 128;
constexpr int BK  = 32;          // 128 bytes per smem row
constexpr int NS  = 3;           // pipeline stages
constexpr int NK  = D_ / BK;     // 64
constexpr int OW  = 4368;
constexpr int NTH = 256;

__device__ __forceinline__ uint32_t smem_u32(const void* p) {
    return (uint32_t)__cvta_generic_to_shared(p);
}
__device__ __forceinline__ void cp16(uint32_t dst, const void* src) {
    asm volatile("cp.async.cg.shared.global [%0], [%1], 16;" :: "r"(dst), "l"(src) : "memory");
}
__device__ __forceinline__ void cp_commit() {
    asm volatile("cp.async.commit_group;" ::: "memory");
}
template <int N>
__device__ __forceinline__ void cp_wait() {
    asm volatile("cp.async.wait_group %0;" :: "n"(N) : "memory");
}
__device__ __forceinline__ void ldsm4(uint32_t& r0, uint32_t& r1, uint32_t& r2, uint32_t& r3,
                                      uint32_t a) {
    asm volatile("ldmatrix.sync.aligned.m8n8.x4.shared.b16 {%0,%1,%2,%3}, [%4];"
                 : "=r"(r0), "=r"(r1), "=r"(r2), "=r"(r3) : "r"(a));
}
__device__ __forceinline__ void mma_tf32(float* c, const uint32_t* a, const uint32_t* b) {
    asm volatile("mma.sync.aligned.m16n8k8.row.col.f32.tf32.tf32.f32 "
                 "{%0,%1,%2,%3}, {%4,%5,%6,%7}, {%8,%9}, {%0,%1,%2,%3};"
                 : "+f"(c[0]), "+f"(c[1]), "+f"(c[2]), "+f"(c[3])
                 : "r"(a[0]), "r"(a[1]), "r"(a[2]), "r"(a[3]), "r"(b[0]), "r"(b[1]));
}

__device__ __forceinline__ float lse16(const float* v) {
    float m = v[0];
#pragma unroll
    for (int j = 1; j < 16; j++) m = fmaxf(m, v[j]);
    float s = 0.f;
#pragma unroll
    for (int j = 0; j < 16; j++) s += __expf(v[j] - m);
    return m + __logf(s);
}

template <int BN, int LEVEL>
__global__ __launch_bounds__(NTH, 2)
void hs_mma(const float* __restrict__ x, const float* __restrict__ W,
            const float* __restrict__ bias, float* __restrict__ out, int B)
{
    constexpr int WARPS_M = (BN == 16) ? 8 : 2;
    constexpr int WM = BM / WARPS_M;            // 16 or 64
    constexpr int WN = (BN == 16) ? 16 : 32;
    constexpr int MT = WM / 16;                 // m16 tiles per warp (1 or 4)
    constexpr int NT = WN / 8;                  // n8 tiles per warp (2 or 4)
    constexpr int A_BYTES = BM * 128;           // 16 KB
    constexpr int B_BYTES = BN * 128;
    constexpr int STAGE   = A_BYTES + B_BYTES;
    constexpr int ACH = BM * 8 / NTH;           // 16B chunks per thread for A (4)
    constexpr int BCH = BN * 8;                 // total B chunks (1024 or 128)
    constexpr int EST = BN + 4;

    extern __shared__ char smc[];
    const uint32_t sb = smem_u32(smc);

    const int tid  = threadIdx.x;
    const int w    = tid >> 5;
    const int lane = tid & 31;
    const int row0 = blockIdx.y * BM;
    const int n0   = blockIdx.x * BN;

    const int wm = (BN == 16) ? w : (w & 1);
    const int wn = (BN == 16) ? 0 : (w >> 1);

    const float* xblk = x + (size_t)row0 * D_;
    const float* wblk = W + (size_t)n0 * D_;

    float c[MT][NT][4];
#pragma unroll
    for (int i = 0; i < MT; i++)
#pragma unroll
        for (int j = 0; j < NT; j++)
#pragma unroll
            for (int k = 0; k < 4; k++) c[i][j][k] = 0.f;

    // ---- cp.async tile loader (stage s, k-block t) ----
    auto load_tile = [&](int s, int t) {
        const int k0 = t * BK;
        const uint32_t as = sb + s * STAGE;
        const uint32_t bs = as + A_BYTES;
#pragma unroll
        for (int i = 0; i < ACH; i++) {
            int cidx = tid + i * NTH;
            int r = cidx >> 3, kq = cidx & 7;
            cp16(as + r * 128 + ((kq ^ (r & 7)) << 4),
                 xblk + (size_t)r * D_ + k0 + kq * 4);
        }
        if (BCH >= NTH) {
#pragma unroll
            for (int i = 0; i < BCH / NTH; i++) {
                int cidx = tid + i * NTH;
                int r = cidx >> 3, kq = cidx & 7;
                cp16(bs + r * 128 + ((kq ^ (r & 7)) << 4),
                     wblk + (size_t)r * D_ + k0 + kq * 4);
            }
        } else {
            if (tid < BCH) {
                int r = tid >> 3, kq = tid & 7;
                cp16(bs + r * 128 + ((kq ^ (r & 7)) << 4),
                     wblk + (size_t)r * D_ + k0 + kq * 4);
            }
        }
    };

    // ldmatrix lane addressing precompute
    const int sel = lane >> 3, lr = lane & 7;
    const int a_row_off = ((sel & 1) << 3) + lr;   // + mt*16 + wm*WM
    const int a_c16_off = (sel >> 1);              // + ks*2
    const int b_row_off = ((sel >> 1) << 3) + lr;  // + np*16 + wn*WN
    const int b_c16_off = (sel & 1);               // + ks*2

    // ---- prologue ----
    load_tile(0, 0); cp_commit();
    load_tile(1, 1); cp_commit();

    for (int t = 0; t < NK; t++) {
        cp_wait<NS - 2>();
        __syncthreads();

        const int s = t % NS;
        const uint32_t as = sb + s * STAGE;
        const uint32_t bs = as + A_BYTES;

#pragma unroll
        for (int ks = 0; ks < BK / 8; ks++) {
            uint32_t af[MT][4];
#pragma unroll
            for (int mt = 0; mt < MT; mt++) {
                int row = wm * WM + mt * 16 + a_row_off;
                int c16 = ks * 2 + a_c16_off;
                ldsm4(af[mt][0], af[mt][1], af[mt][2], af[mt][3],
                      as + row * 128 + (((c16 ^ lr) & 7) << 4));
            }
            uint32_t bf[NT][2];
#pragma unroll
            for (int np = 0; np < NT / 2; np++) {
                int row = wn * WN + np * 16 + b_row_off;
                int c16 = ks * 2 + b_c16_off;
                uint32_t r0, r1, r2, r3;
                ldsm4(r0, r1, r2, r3, bs + row * 128 + (((c16 ^ lr) & 7) << 4));
                bf[np * 2][0] = r0; bf[np * 2][1] = r1;
                bf[np * 2 + 1][0] = r2; bf[np * 2 + 1][1] = r3;
            }
#pragma unroll
            for (int mt = 0; mt < MT; mt++)
#pragma unroll
                for (int nt = 0; nt < NT; nt++)
                    mma_tf32(c[mt][nt], af[mt], bf[nt]);
        }

        __syncthreads();
        if (t + NS - 1 < NK) load_tile((t + NS - 1) % NS, t + NS - 1);
        cp_commit();
    }

    cp_wait<0>();
    __syncthreads();

    // ---- epilogue: frags(+bias) -> smem ----
    float* S = (float*)smc;   // [BM][EST]
    const int g = lane >> 2, tq = lane & 3;
#pragma unroll
    for (int nt = 0; nt < NT; nt++) {
        const int col = wn * WN + nt * 8 + tq * 2;
        const float b0 = __ldg(&bias[n0 + col]);
        const float b1 = __ldg(&bias[n0 + col + 1]);
#pragma unroll
        for (int mt = 0; mt < MT; mt++) {
            const int row = wm * WM + mt * 16 + g;
            S[row * EST + col]           = c[mt][nt][0] + b0;
            S[row * EST + col + 1]       = c[mt][nt][1] + b1;
            S[(row + 8) * EST + col]     = c[mt][nt][2] + b0;
            S[(row + 8) * EST + col + 1] = c[mt][nt][3] + b1;
        }
    }
    __syncthreads();

    // ---- group-of-16 log-softmax (+parent chain), in place ----
    constexpr int GROUPS = BN / 16;
    for (int task = tid; task < BM * GROUPS; task += NTH) {
        const int rr = (GROUPS == 1) ? task : (task >> 3);
        const int gg = (GROUPS == 1) ? 0 : (task & 7);
        float* p = S + rr * EST + gg * 16;
        const float lse = lse16(p);
        const int grow = row0 + rr;
        const int gc   = n0 + gg * 16;
        float pl = 0.f;
        if (LEVEL == 1) pl = out[(size_t)grow * OW + (gc >> 4)];
        if (LEVEL == 2) pl = out[(size_t)grow * OW + 16 + (gc >> 4)];
        const float adj = pl - lse;
#pragma unroll
        for (int j = 0; j < 16; j++) p[j] += adj;
    }
    __syncthreads();

    // ---- coalesced store-out ----
    constexpr int F4 = BN / 4;
    for (int idx = tid; idx < BM * F4; idx += NTH) {
        const int rr = idx / F4, c4 = idx % F4;
        float4 val = *reinterpret_cast<const float4*>(S + rr * EST + c4 * 4);
        const int gr = row0 + rr;
        const int gc = n0 + c4 * 4;
        if (LEVEL == 0)
            *reinterpret_cast<float4*>(out + (size_t)gr * OW + gc) = val;
        if (LEVEL == 1)
            *reinterpret_cast<float4*>(out + (size_t)gr * OW + 16 + gc) = val;
        if (LEVEL == 2) {
            *reinterpret_cast<float4*>(out + (size_t)gr * OW + 272 + gc) = val;
            *reinterpret_cast<float4*>(out + (size_t)B * OW + (size_t)gr * 4096 + gc) = val;
        }
    }
}

} // namespace

extern "C" void kernel_launch(void* const* d_in, const int* in_sizes, int n_in,
                              void* d_out, int out_size)
{
    const float* x  = (const float*)d_in[0];
    const float* W0 = (const float*)d_in[1];
    const float* b0 = (const float*)d_in[2];
    const float* W1 = (const float*)d_in[3];
    const float* b1 = (const float*)d_in[4];
    const float* W2 = (const float*)d_in[5];
    const float* b2 = (const float*)d_in[6];
    float* out = (float*)d_out;
    const int B = in_sizes[0] / D_;   // 4096

    constexpr int SM_BIG = NS * (128 * 128 + 128 * 128);          // 98304
    constexpr int EPI_BIG = 128 * (128 + 4) * 4;                  // 67584
    constexpr int DYN_BIG = (SM_BIG > EPI_BIG) ? SM_BIG : EPI_BIG;
    constexpr int SM_SM  = NS * (128 * 128 + 16 * 128);           // 55296
    constexpr int EPI_SM = 128 * (16 + 4) * 4;
    constexpr int DYN_SM = (SM_SM > EPI_SM) ? SM_SM : EPI_SM;

    cudaFuncSetAttribute((const void*)hs_mma<16, 0>,
                         cudaFuncAttributeMaxDynamicSharedMemorySize, DYN_SM);
    cudaFuncSetAttribute((const void*)hs_mma<128, 1>,
                         cudaFuncAttributeMaxDynamicSharedMemorySize, DYN_BIG);
    cudaFuncSetAttribute((const void*)hs_mma<128, 2>,
                         cudaFuncAttributeMaxDynamicSharedMemorySize, DYN_BIG);

    dim3 blk(NTH);
    hs_mma<16, 0><<<dim3(1,  B / BM), blk, DYN_SM>>>(x, W0, b0, out, B);
    hs_mma<128, 1><<<dim3(2,  B / BM), blk, DYN_BIG>>>(x, W1, b1, out, B);
    hs_mma<128, 2><<<dim3(32, B / BM), blk, DYN_BIG>>>(x, W2, b2, out, B);
}

// round 4
// speedup vs baseline: 4.2355x; 1.0817x over previous
#include <cuda_runtime.h>
#include <cstdint>
#include <math.h>

// HierarchicalSoftmax, levels [16,256,4096], D=2048, B=4096.
// tf32 mma.sync + cp.async pipeline + fused group-of-16 log-softmax.
//   K0 (SIMT): lp0 -> out[:,0:16]                       (256 CTAs)
//   K1 (mma):  lp1 = lsm16(x@W1^T+b1)+lp0 -> out[:,16:272]
//   K2 (mma):  lp2 = lsm16(x@W2^T+b2)+lp1 -> out[:,272:4368] and out[B*OW:]

namespace {

constexpr int D_  = 2048;
constexpr int BK  = 32;          // 128 bytes per smem row
constexpr int NS  = 3;           // pipeline stages
constexpr int NK  = D_ / BK;     // 64
constexpr int OW  = 4368;

__device__ __forceinline__ uint32_t smem_u32(const void* p) {
    return (uint32_t)__cvta_generic_to_shared(p);
}
__device__ __forceinline__ void cp16(uint32_t dst, const void* src) {
    asm volatile("cp.async.cg.shared.global [%0], [%1], 16;" :: "r"(dst), "l"(src) : "memory");
}
__device__ __forceinline__ void cp_commit() {
    asm volatile("cp.async.commit_group;" ::: "memory");
}
template <int N>
__device__ __forceinline__ void cp_wait() {
    asm volatile("cp.async.wait_group %0;" :: "n"(N) : "memory");
}
__device__ __forceinline__ void ldsm4(uint32_t& r0, uint32_t& r1, uint32_t& r2, uint32_t& r3,
                                      uint32_t a) {
    asm volatile("ldmatrix.sync.aligned.m8n8.x4.shared.b16 {%0,%1,%2,%3}, [%4];"
                 : "=r"(r0), "=r"(r1), "=r"(r2), "=r"(r3) : "r"(a));
}
__device__ __forceinline__ void mma_tf32(float* c, const uint32_t* a, const uint32_t* b) {
    asm volatile("mma.sync.aligned.m16n8k8.row.col.f32.tf32.tf32.f32 "
                 "{%0,%1,%2,%3}, {%4,%5,%6,%7}, {%8,%9}, {%0,%1,%2,%3};"
                 : "+f"(c[0]), "+f"(c[1]), "+f"(c[2]), "+f"(c[3])
                 : "r"(a[0]), "r"(a[1]), "r"(a[2]), "r"(a[3]), "r"(b[0]), "r"(b[1]));
}

__device__ __forceinline__ float lse16(const float* v) {
    float m = v[0];
#pragma unroll
    for (int j = 1; j < 16; j++) m = fmaxf(m, v[j]);
    float s = 0.f;
#pragma unroll
    for (int j = 0; j < 16; j++) s += __expf(v[j] - m);
    return m + __logf(s);
}

// ---------------------------------------------------------------------------
// K0: level 0 (N=16) — SIMT, 16 rows per CTA, 256 CTAs.
// ---------------------------------------------------------------------------
__global__ __launch_bounds__(256)
void hs_l0(const float* __restrict__ x, const float* __restrict__ W0,
           const float* __restrict__ b0, float* __restrict__ out)
{
    constexpr int KC = 128;               // K chunk
    constexpr int NC = D_ / KC;           // 16 chunks
    __shared__ float xs[2][16][KC + 4];
    __shared__ float ws[2][16][KC + 4];
    __shared__ float lg[16][17];
    __shared__ float lsev[16];

    const int tid  = threadIdx.x;
    const int row0 = blockIdx.x * 16;
    const float* xblk = x + (size_t)row0 * D_;

    auto load = [&](int buf, int k0) {
#pragma unroll
        for (int i = 0; i < 2; i++) {
            int idx = tid + i * 256;              // 512 float4 per matrix
            int r = idx >> 5, q = idx & 31;
            cp16(smem_u32(&xs[buf][r][q * 4]), xblk + (size_t)r * D_ + k0 + q * 4);
            cp16(smem_u32(&ws[buf][r][q * 4]), W0 + (size_t)r * D_ + k0 + q * 4);
        }
    };

    const int r = tid & 15, c = tid >> 4;
    float acc = 0.f;

    load(0, 0); cp_commit();
    for (int t = 0; t < NC; t++) {
        if (t + 1 < NC) { load((t + 1) & 1, (t + 1) * KC); cp_commit(); cp_wait<1>(); }
        else            { cp_wait<0>(); }
        __syncthreads();
        const float* xr = xs[t & 1][r];
        const float* wr = ws[t & 1][c];
#pragma unroll
        for (int k = 0; k < KC; k += 4) {
            float4 xa = *reinterpret_cast<const float4*>(xr + k);
            float4 wb = *reinterpret_cast<const float4*>(wr + k);
            acc += xa.x * wb.x + xa.y * wb.y + xa.z * wb.z + xa.w * wb.w;
        }
        __syncthreads();
    }

    lg[r][c] = acc + __ldg(&b0[c]);
    __syncthreads();
    if (tid < 16) lsev[tid] = lse16(lg[tid]);
    __syncthreads();
    out[(size_t)(row0 + r) * OW + c] = lg[r][c] - lsev[r];
}

// ---------------------------------------------------------------------------
// K1/K2: tf32 mma GEMM + fused epilogue.
// ---------------------------------------------------------------------------
template <int BM, int BN, int NTH, int WGM, int WGN, int LEVEL>
__global__ __launch_bounds__(NTH, 2)
void hs_mma(const float* __restrict__ x, const float* __restrict__ W,
            const float* __restrict__ bias, float* __restrict__ out, int B)
{
    constexpr int WM = BM / WGM;
    constexpr int WN = BN / WGN;
    constexpr int MT = WM / 16;
    constexpr int NT = WN / 8;
    constexpr int A_BYTES = BM * 128;
    constexpr int B_BYTES = BN * 128;
    constexpr int STAGE   = A_BYTES + B_BYTES;
    constexpr int ACH = BM * 8 / NTH;
    constexpr int BCH = BN * 8 / NTH;
    constexpr int EST = BN + 4;

    extern __shared__ char smc[];
    const uint32_t sb = smem_u32(smc);

    const int tid  = threadIdx.x;
    const int w    = tid >> 5;
    const int lane = tid & 31;
    const int row0 = blockIdx.y * BM;
    const int n0   = blockIdx.x * BN;

    const int wm = w % WGM;
    const int wn = w / WGM;

    const float* xblk = x + (size_t)row0 * D_;
    const float* wblk = W + (size_t)n0 * D_;

    float c[MT][NT][4];
#pragma unroll
    for (int i = 0; i < MT; i++)
#pragma unroll
        for (int j = 0; j < NT; j++)
#pragma unroll
            for (int k = 0; k < 4; k++) c[i][j][k] = 0.f;

    auto load_tile = [&](int s, int t) {
        const int k0 = t * BK;
        const uint32_t as = sb + s * STAGE;
        const uint32_t bs = as + A_BYTES;
#pragma unroll
        for (int i = 0; i < ACH; i++) {
            int cidx = tid + i * NTH;
            int r = cidx >> 3, kq = cidx & 7;
            cp16(as + r * 128 + ((kq ^ (r & 7)) << 4),
                 xblk + (size_t)r * D_ + k0 + kq * 4);
        }
#pragma unroll
        for (int i = 0; i < BCH; i++) {
            int cidx = tid + i * NTH;
            int r = cidx >> 3, kq = cidx & 7;
            cp16(bs + r * 128 + ((kq ^ (r & 7)) << 4),
                 wblk + (size_t)r * D_ + k0 + kq * 4);
        }
    };

    const int sel = lane >> 3, lr = lane & 7;
    const int a_row_off = ((sel & 1) << 3) + lr;
    const int a_c16_off = (sel >> 1);
    const int b_row_off = ((sel >> 1) << 3) + lr;
    const int b_c16_off = (sel & 1);

    load_tile(0, 0); cp_commit();
    load_tile(1, 1); cp_commit();

    for (int t = 0; t < NK; t++) {
        cp_wait<NS - 2>();
        __syncthreads();

        const int s = t % NS;
        const uint32_t as = sb + s * STAGE;
        const uint32_t bs = as + A_BYTES;

#pragma unroll
        for (int ks = 0; ks < BK / 8; ks++) {
            uint32_t af[MT][4];
#pragma unroll
            for (int mt = 0; mt < MT; mt++) {
                int row = wm * WM + mt * 16 + a_row_off;
                int c16 = ks * 2 + a_c16_off;
                ldsm4(af[mt][0], af[mt][1], af[mt][2], af[mt][3],
                      as + row * 128 + (((c16 ^ lr) & 7) << 4));
            }
            uint32_t bf[NT][2];
#pragma unroll
            for (int np = 0; np < NT / 2; np++) {
                int row = wn * WN + np * 16 + b_row_off;
                int c16 = ks * 2 + b_c16_off;
                uint32_t r0, r1, r2, r3;
                ldsm4(r0, r1, r2, r3, bs + row * 128 + (((c16 ^ lr) & 7) << 4));
                bf[np * 2][0] = r0; bf[np * 2][1] = r1;
                bf[np * 2 + 1][0] = r2; bf[np * 2 + 1][1] = r3;
            }
#pragma unroll
            for (int mt = 0; mt < MT; mt++)
#pragma unroll
                for (int nt = 0; nt < NT; nt++)
                    mma_tf32(c[mt][nt], af[mt], bf[nt]);
        }

        __syncthreads();
        if (t + NS - 1 < NK) load_tile((t + NS - 1) % NS, t + NS - 1);
        cp_commit();
    }

    cp_wait<0>();
    __syncthreads();

    // frags (+bias) -> smem
    float* S = (float*)smc;   // [BM][EST]
    const int g = lane >> 2, tq = lane & 3;
#pragma unroll
    for (int nt = 0; nt < NT; nt++) {
        const int col = wn * WN + nt * 8 + tq * 2;
        const float b0 = __ldg(&bias[n0 + col]);
        const float b1 = __ldg(&bias[n0 + col + 1]);
#pragma unroll
        for (int mt = 0; mt < MT; mt++) {
            const int row = wm * WM + mt * 16 + g;
            S[row * EST + col]           = c[mt][nt][0] + b0;
            S[row * EST + col + 1]       = c[mt][nt][1] + b1;
            S[(row + 8) * EST + col]     = c[mt][nt][2] + b0;
            S[(row + 8) * EST + col + 1] = c[mt][nt][3] + b1;
        }
    }
    __syncthreads();

    // group-of-16 log-softmax (+parent chain), in place
    constexpr int GROUPS = BN / 16;
    for (int task = tid; task < BM * GROUPS; task += NTH) {
        const int rr = task >> 3;            // GROUPS == 8 for BN=128
        const int gg = task & 7;
        float* p = S + rr * EST + gg * 16;
        const float lse = lse16(p);
        const int grow = row0 + rr;
        const int gc   = n0 + gg * 16;
        float pl = 0.f;
        if (LEVEL == 1) pl = out[(size_t)grow * OW + (gc >> 4)];
        if (LEVEL == 2) pl = out[(size_t)grow * OW + 16 + (gc >> 4)];
        const float adj = pl - lse;
#pragma unroll
        for (int j = 0; j < 16; j++) p[j] += adj;
    }
    __syncthreads();

    // coalesced store-out
    constexpr int F4 = BN / 4;
    for (int idx = tid; idx < BM * F4; idx += NTH) {
        const int rr = idx / F4, c4 = idx % F4;
        float4 val = *reinterpret_cast<const float4*>(S + rr * EST + c4 * 4);
        const int gr = row0 + rr;
        const int gc = n0 + c4 * 4;
        if (LEVEL == 1)
            *reinterpret_cast<float4*>(out + (size_t)gr * OW + 16 + gc) = val;
        if (LEVEL == 2) {
            *reinterpret_cast<float4*>(out + (size_t)gr * OW + 272 + gc) = val;
            *reinterpret_cast<float4*>(out + (size_t)B * OW + (size_t)gr * 4096 + gc) = val;
        }
    }
}

} // namespace

extern "C" void kernel_launch(void* const* d_in, const int* in_sizes, int n_in,
                              void* d_out, int out_size)
{
    const float* x  = (const float*)d_in[0];
    const float* W0 = (const float*)d_in[1];
    const float* b0 = (const float*)d_in[2];
    const float* W1 = (const float*)d_in[3];
    const float* b1 = (const float*)d_in[4];
    const float* W2 = (const float*)d_in[5];
    const float* b2 = (const float*)d_in[6];
    float* out = (float*)d_out;
    const int B = in_sizes[0] / D_;   // 4096

    // K1: BM=32, BN=128, 4 warps (warp grid 1x4, warp tile 32x32)
    constexpr int SM_K1 = NS * (32 * 128 + 128 * 128);     // 61440
    constexpr int EPI_K1 = 32 * (128 + 4) * 4;             // 16896
    constexpr int DYN_K1 = (SM_K1 > EPI_K1) ? SM_K1 : EPI_K1;
    // K2: BM=128, BN=128, 4 warps (warp grid 2x2, warp tile 64x64)
    constexpr int SM_K2 = NS * (128 * 128 + 128 * 128);    // 98304
    constexpr int EPI_K2 = 128 * (128 + 4) * 4;            // 67584
    constexpr int DYN_K2 = (SM_K2 > EPI_K2) ? SM_K2 : EPI_K2;

    cudaFuncSetAttribute((const void*)hs_mma<32, 128, 128, 1, 4, 1>,
                         cudaFuncAttributeMaxDynamicSharedMemorySize, DYN_K1);
    cudaFuncSetAttribute((const void*)hs_mma<128, 128, 128, 2, 2, 2>,
                         cudaFuncAttributeMaxDynamicSharedMemorySize, DYN_K2);

    hs_l0<<<B / 16, 256>>>(x, W0, b0, out);
    hs_mma<32, 128, 128, 1, 4, 1><<<dim3(2,  B / 32),  128, DYN_K1>>>(x, W1, b1, out, B);
    hs_mma<128, 128, 128, 2, 2, 2><<<dim3(32, B / 128), 128, DYN_K2>>>(x, W2, b2, out, B);
}